// round 2
// baseline (speedup 1.0000x reference)
#include <cuda_runtime.h>
#include <cstddef>

#define RLA_EPS 1e-6f

__device__ __forceinline__ float elu1(float x) {
    // elu(x) + 1  ==  x>0 ? x+1 : exp(x)
    return x > 0.0f ? x + 1.0f : __expf(x);
}

// Two CTAs per (b,n) pair, each handling half of the M columns.
// 256 threads: 8 d-subgroups x 32 float4-column lanes.
// Phase 1: Q/K feature maps, Zi_new, shuffle-reduced normalizer Z (recomputed
//          by both halves; only half 0 stores Zi_new).
// Phase 2: stream the Si half-tile [D, M/2] once as float4, rank-1 update,
//          accumulate V columns locally.
__global__ __launch_bounds__(256, 8)
void rla_kernel(const float* __restrict__ q,
                const float* __restrict__ k,
                const float* __restrict__ v,
                const float* __restrict__ Si,
                const float* __restrict__ Zi,
                float* __restrict__ outV,    // [BN, M]
                float* __restrict__ outSi,   // [BN, D, M]
                float* __restrict__ outZi,   // [BN, D]
                int D, int M)
{
    const int bn   = blockIdx.x >> 1;
    const int half = blockIdx.x & 1;
    const int tid  = threadIdx.x;

    __shared__ float sQ[256];
    __shared__ float sK[256];
    __shared__ float swred[8];
    __shared__ float sZ;
    __shared__ float4 sacc[256];  // cross-d-group reduction buffer

    const size_t rowD = (size_t)bn * D;
    const size_t rowM = (size_t)bn * M;
    const size_t tile = (size_t)bn * D * M;

    // ---------------- Phase 1: feature maps + normalizer ----------------
    const int lane32 = tid & 31;
    const int warp   = tid >> 5;

    float part = 0.0f;
    for (int d = tid; d < D; d += blockDim.x) {
        float Qd = elu1(q[rowD + d]);
        float Kd = elu1(k[rowD + d]);
        float zn = Zi[rowD + d] + Kd;
        if (half == 0) outZi[rowD + d] = zn;
        sQ[d] = Qd;
        sK[d] = Kd;
        part += Qd * zn;
    }
    #pragma unroll
    for (int o = 16; o > 0; o >>= 1)
        part += __shfl_down_sync(0xffffffffu, part, o);
    if (lane32 == 0) swred[warp] = part;
    __syncthreads();
    if (tid == 0) {
        float s = 0.0f;
        #pragma unroll
        for (int w = 0; w < 8; w++) s += swred[w];
        sZ = 1.0f / (s + RLA_EPS);
    }
    __syncthreads();
    const float Z = sZ;

    // ---------------- Phase 2: stream Si half-tile ----------------------
    const int M4    = M >> 2;          // float4 columns in the full row
    const int HM4   = M4 >> 1;         // columns handled by this CTA (32)
    const int lane  = tid & 31;        // column lane within the half
    const int ty    = tid >> 5;        // d-subgroup 0..7
    const int m4    = half * HM4 + lane;

    const float4* Si4 = (const float4*)(Si    + tile);
    float4*       So4 = (float4*)      (outSi + tile);
    const float4* v4p = (const float4*)(v     + rowM);
    float4*       V4  = (float4*)      (outV  + rowM);

    const float4 v4 = v4p[m4];
    float4 acc = make_float4(0.f, 0.f, 0.f, 0.f);

    #pragma unroll 8
    for (int d = ty; d < D; d += 8) {
        const size_t idx = (size_t)d * M4 + m4;
        float4 s = __ldcs(&Si4[idx]);
        const float kd = sK[d];
        const float qd = sQ[d];
        s.x = fmaf(kd, v4.x, s.x);
        s.y = fmaf(kd, v4.y, s.y);
        s.z = fmaf(kd, v4.z, s.z);
        s.w = fmaf(kd, v4.w, s.w);
        __stcs(&So4[idx], s);
        acc.x = fmaf(qd, s.x, acc.x);
        acc.y = fmaf(qd, s.y, acc.y);
        acc.z = fmaf(qd, s.z, acc.z);
        acc.w = fmaf(qd, s.w, acc.w);
    }

    sacc[tid] = acc;
    __syncthreads();
    if (ty == 0) {
        float4 out = make_float4(0.f, 0.f, 0.f, 0.f);
        #pragma unroll
        for (int j = 0; j < 8; j++) {
            float4 a = sacc[lane + 32 * j];
            out.x += a.x; out.y += a.y; out.z += a.z; out.w += a.w;
        }
        out.x *= Z; out.y *= Z; out.z *= Z; out.w *= Z;
        V4[m4] = out;
    }
}

extern "C" void kernel_launch(void* const* d_in, const int* in_sizes, int n_in,
                              void* d_out, int out_size)
{
    const float* q  = (const float*)d_in[0];
    const float* k  = (const float*)d_in[1];
    const float* v  = (const float*)d_in[2];
    const float* Si = (const float*)d_in[3];
    const float* Zi = (const float*)d_in[4];

    const long long nQ  = in_sizes[0];  // BN * D
    const long long nV  = in_sizes[2];  // BN * M
    const long long nSi = in_sizes[3];  // BN * D * M

    const int D  = (int)(nSi / nV);
    const int M  = (int)(nSi / nQ);
    const int BN = (int)(nQ / D);

    float* out   = (float*)d_out;
    float* outV  = out;                 // [BN, M]
    float* outSi = out + nV;            // [BN, D, M]
    float* outZi = out + nV + nSi;      // [BN, D]

    rla_kernel<<<BN * 2, 256>>>(q, k, v, Si, Zi, outV, outSi, outZi, D, M);
}